// round 1
// baseline (speedup 1.0000x reference)
#include <cuda_runtime.h>
#include <math.h>
#include <stdint.h>

#define PDIM 224
#define PP   (PDIM*PDIM)
#define BATCH 128
#define NMODE 35
#define NIMG  256          // 128 batch * 2 variants, img = 2*b + var
#define CW    16           // columns per chunk in col pass
#define CHUNKS (PDIM/CW)   // 14
#define PI_F 3.14159265358979323846f

// ---------------- scratch (static device globals; no runtime alloc) ----------
__device__ float  g_phase[BATCH * PP];          // 25.7 MB
__device__ float2 g_work [NIMG  * PP];          // 102.8 MB row-FFT intermediate
__device__ float  g_part [NIMG * CHUNKS * 4];   // per-(img,chunk): S, A, C, T2

// ---------------- radix-7 twiddle tables: cos/sin(2*pi*m/7) ------------------
__device__ const float C7[7] = {
    1.0f,
    0.62348980185873359f, -0.22252093395631440f, -0.90096886790241915f,
   -0.90096886790241915f, -0.22252093395631440f,  0.62348980185873359f
};
__device__ const float S7[7] = {
    0.0f,
    0.78183148246802981f,  0.97492791218182362f,  0.43388373911755812f,
   -0.43388373911755812f, -0.97492791218182362f, -0.78183148246802981f
};

__device__ __forceinline__ float2 cmulf(float2 a, float2 b) {
    return make_float2(a.x*b.x - a.y*b.y, a.x*b.y + a.y*b.x);
}

// 224-point forward FFT (e^{-i}) held by one warp.
// Input:  v[j] = x[32*j + lane], j=0..6
// Output: v[k1] = X[7*bitrev5(lane) + k1]
__device__ __forceinline__ void fft224(float2 v[7], int lane) {
    // --- radix-7 DFT within thread: b[k] = sum_j v[j] * W7^{j k} (W7=e^{-2pi i/7})
    float2 b[7];
#pragma unroll
    for (int k = 0; k < 7; k++) {
        float br = 0.f, bi = 0.f;
#pragma unroll
        for (int j = 0; j < 7; j++) {
            const int idx = (j * k) % 7;     // compile-time after unroll
            const float c = C7[idx], s = S7[idx];
            // (vx + i vy) * (c - i s)
            br += v[j].x * c + v[j].y * s;
            bi += v[j].y * c - v[j].x * s;
        }
        b[k] = make_float2(br, bi);
    }
    // --- twiddle W224^{lane*k1}, built incrementally
    float sa, ca;
    sincosf(-2.0f * PI_F * (float)lane / 224.0f, &sa, &ca);
    float2 step = make_float2(ca, sa);
    float2 w = make_float2(1.f, 0.f);
#pragma unroll
    for (int k = 0; k < 7; k++) {
        v[k] = cmulf(b[k], w);
        w = cmulf(w, step);
    }
    // --- 32-point cross-lane DIF radix-2 (5 stages), output bit-reversed
#pragma unroll
    for (int h = 16; h > 0; h >>= 1) {
        float sh, ch;
        sincosf(-PI_F * (float)(lane & (h - 1)) / (float)h, &sh, &ch);
        const float2 tw = make_float2(ch, sh);
        const bool hi = (lane & h) != 0;
#pragma unroll
        for (int k = 0; k < 7; k++) {
            float2 o;
            o.x = __shfl_xor_sync(0xffffffffu, v[k].x, h);
            o.y = __shfl_xor_sync(0xffffffffu, v[k].y, h);
            if (hi) {
                float2 d = make_float2(o.x - v[k].x, o.y - v[k].y);
                v[k] = cmulf(d, tw);
            } else {
                v[k].x += o.x;
                v[k].y += o.y;
            }
        }
    }
}

// ---------------- kernel 1: phase = (pred @ zernike) * mask ------------------
__global__ __launch_bounds__(256) void phase_kernel(
    const float* __restrict__ pred,
    const float* __restrict__ zern,
    const float* __restrict__ mask)
{
    __shared__ float sp[BATCH][36];   // padded rows (144B, 16B aligned)
    const int tid = threadIdx.x;
    for (int i = tid; i < BATCH * NMODE; i += 256)
        sp[i / NMODE][i % NMODE] = pred[i];
    __syncthreads();

    const int p = blockIdx.x * 256 + tid;   // 196*256 == 50176 exactly
    float z[NMODE];
#pragma unroll
    for (int m = 0; m < NMODE; m++) z[m] = zern[(size_t)m * PP + p];
    const float mk = mask[p];

    for (int b = 0; b < BATCH; b++) {
        const float4* pb = reinterpret_cast<const float4*>(&sp[b][0]);
        float acc = 0.f;
#pragma unroll
        for (int q = 0; q < 8; q++) {
            float4 f = pb[q];
            acc += f.x * z[4*q+0] + f.y * z[4*q+1] + f.z * z[4*q+2] + f.w * z[4*q+3];
        }
        acc += sp[b][32] * z[32] + sp[b][33] * z[33] + sp[b][34] * z[34];
        g_phase[(size_t)b * PP + p] = acc * mk;
    }
}

// ---------------- kernel 2: per-row field + row FFT (both variants) ----------
__global__ __launch_bounds__(256) void row_kernel(const float* __restrict__ mask)
{
    const int gw   = blockIdx.x * 8 + (threadIdx.x >> 5);  // 0 .. 128*224-1
    const int lane = threadIdx.x & 31;
    const int b = gw / PDIM;
    const int h = gw % PDIM;

    const float* ph = g_phase + (size_t)b * PP + (size_t)h * PDIM;
    const float y  = (float)h * (2.0f / 223.0f) - 1.0f;
    const float y2 = y * y;

    float phi[7], mk[7], dfc[7];
#pragma unroll
    for (int j = 0; j < 7; j++) {
        const int w = 32 * j + lane;
        phi[j] = ph[w];
        mk[j]  = mask[h * PDIM + w];
        const float x = (float)w * (2.0f / 223.0f) - 1.0f;
        dfc[j] = 2.0f * (x * x + y2) - 1.0f;   // DEFOCUS_RAD = 1.0
    }
    const int rev = (int)(__brev((unsigned)lane) >> 27);

    // variant 0: in-focus
    {
        float2 v[7];
#pragma unroll
        for (int j = 0; j < 7; j++) {
            float s, c; sincosf(phi[j], &s, &c);
            v[j] = make_float2(mk[j] * c, mk[j] * s);
        }
        fft224(v, lane);
        float2* o = g_work + (size_t)(2 * b) * PP + (size_t)h * PDIM + 7 * rev;
#pragma unroll
        for (int k = 0; k < 7; k++) o[k] = v[k];
    }
    // variant 1: defocused
    {
        float2 v[7];
#pragma unroll
        for (int j = 0; j < 7; j++) {
            float s, c; sincosf(phi[j] + dfc[j], &s, &c);
            v[j] = make_float2(mk[j] * c, mk[j] * s);
        }
        fft224(v, lane);
        float2* o = g_work + (size_t)(2 * b + 1) * PP + (size_t)h * PDIM + 7 * rev;
#pragma unroll
        for (int k = 0; k < 7; k++) o[k] = v[k];
    }
}

// ---------------- kernel 3: column FFT + fused psf statistics ----------------
// For each (img, 16-column chunk): column FFTs, then accumulate
//   S = sum psf, A = sum psf^2, C = sum psf * t_shifted, T2 = sum t^2
// (fftshift folded into the t index remap: shifted idx = (idx+112)%224)
__global__ __launch_bounds__(512) void col_kernel(const float* __restrict__ psfs)
{
    const int img   = blockIdx.x / CHUNKS;   // img = 2*b + var
    const int chunk = blockIdx.x % CHUNKS;
    const int v0    = chunk * CW;

    __shared__ float2 tile [PDIM][CW + 1];   // 30464 B
    __shared__ float  ttile[PDIM][CW + 1];   // 15232 B
    __shared__ float  red[16 * 4];

    const int tid = threadIdx.x;
    const float2* src = g_work + (size_t)img * PP;
    const float*  t   = psfs   + (size_t)img * PP;
    const int tc0 = (v0 + 112) % 224;        // chunk-aligned, no wrap within chunk

    for (int i = tid; i < PDIM * CW; i += 512) {
        const int h = i / CW, c = i % CW;
        tile [h][c] = src[h * PDIM + v0 + c];
        ttile[h][c] = t  [h * PDIM + tc0 + c];
    }
    __syncthreads();

    const int warp = tid >> 5, lane = tid & 31;
    float2 v[7];
#pragma unroll
    for (int j = 0; j < 7; j++) v[j] = tile[32 * j + lane][warp];
    fft224(v, lane);

    const int rev = (int)(__brev((unsigned)lane) >> 27);
    float S = 0.f, A = 0.f, C = 0.f, T2 = 0.f;
#pragma unroll
    for (int k = 0; k < 7; k++) {
        const int u  = 7 * rev + k;
        const int us = (u >= 112) ? (u - 112) : (u + 112);
        const float p  = v[k].x * v[k].x + v[k].y * v[k].y;
        const float tv = ttile[us][warp];
        S += p; A += p * p; C += p * tv; T2 += tv * tv;
    }
#pragma unroll
    for (int off = 16; off > 0; off >>= 1) {
        S  += __shfl_down_sync(0xffffffffu, S,  off);
        A  += __shfl_down_sync(0xffffffffu, A,  off);
        C  += __shfl_down_sync(0xffffffffu, C,  off);
        T2 += __shfl_down_sync(0xffffffffu, T2, off);
    }
    if (lane == 0) {
        red[warp * 4 + 0] = S;  red[warp * 4 + 1] = A;
        red[warp * 4 + 2] = C;  red[warp * 4 + 3] = T2;
    }
    __syncthreads();
    if (tid == 0) {
        float s = 0.f, a = 0.f, c = 0.f, t2 = 0.f;
#pragma unroll
        for (int w = 0; w < 16; w++) {
            s += red[w * 4 + 0]; a += red[w * 4 + 1];
            c += red[w * 4 + 2]; t2 += red[w * 4 + 3];
        }
        float* dst = g_part + (size_t)blockIdx.x * 4;
        dst[0] = s; dst[1] = a; dst[2] = c; dst[3] = t2;
    }
}

// ---------------- kernel 4: z_loss + deterministic final combine -------------
__global__ __launch_bounds__(256) void final_kernel(
    const float* __restrict__ pred,
    const float* __restrict__ target,
    float* __restrict__ out)
{
    __shared__ float sh[256];
    const int tid = threadIdx.x;

    // sign-weighted MSE partial
    float zs = 0.f;
    for (int i = tid; i < BATCH * NMODE; i += 256) {
        const float p = pred[i], t = target[i];
        const float d = p - t;
        const float w = (p * t < 0.f) ? 10.0f : 1.0f;  // sign(p)sign(t)<0 <=> p*t<0
        zs += d * d * w;
    }
    // per-image recon contribution: A/S'^2 - 2C/S' + T2
    float rc = 0.f;
    if (tid < NIMG) {
        float s = 0.f, a = 0.f, c = 0.f, t2 = 0.f;
        for (int ch = 0; ch < CHUNKS; ch++) {
            const float* q = g_part + (size_t)(tid * CHUNKS + ch) * 4;
            s += q[0]; a += q[1]; c += q[2]; t2 += q[3];
        }
        const float sp = s + 1e-8f;
        rc = a / (sp * sp) - 2.0f * c / sp + t2;
    }

    sh[tid] = zs; __syncthreads();
    for (int off = 128; off > 0; off >>= 1) {
        if (tid < off) sh[tid] += sh[tid + off];
        __syncthreads();
    }
    const float zloss = sh[0] / (float)(BATCH * NMODE);
    __syncthreads();

    sh[tid] = rc; __syncthreads();
    for (int off = 128; off > 0; off >>= 1) {
        if (tid < off) sh[tid] += sh[tid + off];
        __syncthreads();
    }
    if (tid == 0) {
        const float recon = sh[0] / ((float)BATCH * (float)PP);
        out[0] = zloss + 0.4f * recon;
    }
}

// ---------------- launch ------------------------------------------------------
extern "C" void kernel_launch(void* const* d_in, const int* in_sizes, int n_in,
                              void* d_out, int out_size)
{
    const float* pred   = (const float*)d_in[0];
    const float* target = (const float*)d_in[1];
    const float* psfs   = (const float*)d_in[2];
    const float* zern   = (const float*)d_in[3];
    const float* mask   = (const float*)d_in[4];
    float* out = (float*)d_out;

    phase_kernel<<<196, 256>>>(pred, zern, mask);
    row_kernel  <<<BATCH * PDIM / 8, 256>>>(mask);
    col_kernel  <<<NIMG * CHUNKS, 512>>>(psfs);
    final_kernel<<<1, 256>>>(pred, target, out);
}

// round 2
// speedup vs baseline: 1.3529x; 1.3529x over previous
#include <cuda_runtime.h>
#include <cuda_fp16.h>
#include <math.h>
#include <stdint.h>

#define PDIM 224
#define PP   (PDIM*PDIM)
#define BATCH 128
#define NMODE 35
#define NIMG  256          // 128 batch * 2 variants, img = 2*b + var
#define CW    16           // columns per chunk in col pass
#define CHUNKS (PDIM/CW)   // 14
#define PI_F 3.14159265358979323846f

// ---------------- scratch (static device globals; no runtime alloc) ----------
__device__ float   g_phase[BATCH * PP];            // 25.7 MB fp32
__device__ __half2 g_work [NIMG  * PP];            // 51.4 MB row-FFT intermediate
__device__ float   g_part [CHUNKS * NIMG * 4];     // [chunk][img]{S,A,C,T2}

// ---------------- radix-7 twiddle tables: cos/sin(2*pi*m/7) ------------------
__device__ const float C7[7] = {
    1.0f,
    0.62348980185873359f, -0.22252093395631440f, -0.90096886790241915f,
   -0.90096886790241915f, -0.22252093395631440f,  0.62348980185873359f
};
__device__ const float S7[7] = {
    0.0f,
    0.78183148246802981f,  0.97492791218182362f,  0.43388373911755812f,
   -0.43388373911755812f, -0.97492791218182362f, -0.78183148246802981f
};

__device__ __forceinline__ float2 cmulf(float2 a, float2 b) {
    return make_float2(a.x*b.x - a.y*b.y, a.x*b.y + a.y*b.x);
}

// 224-point forward FFT (e^{-i}) held by one warp.
// Input:  v[j] = x[32*j + lane], j=0..6
// Output: v[k1] = X[7*bitrev5(lane) + k1]
__device__ __forceinline__ void fft224(float2 v[7], int lane) {
    // --- radix-7 DFT within thread: b[k] = sum_j v[j] * W7^{j k}
    float2 b[7];
#pragma unroll
    for (int k = 0; k < 7; k++) {
        float br = 0.f, bi = 0.f;
#pragma unroll
        for (int j = 0; j < 7; j++) {
            const int idx = (j * k) % 7;     // compile-time after unroll
            const float c = C7[idx], s = S7[idx];
            br += v[j].x * c + v[j].y * s;
            bi += v[j].y * c - v[j].x * s;
        }
        b[k] = make_float2(br, bi);
    }
    // --- twiddle W224^{lane*k1}, built incrementally (1 sincos)
    float sa, ca;
    __sincosf(-2.0f * PI_F * (float)lane / 224.0f, &sa, &ca);
    float2 step = make_float2(ca, sa);
    float2 w = make_float2(1.f, 0.f);
#pragma unroll
    for (int k = 0; k < 7; k++) {
        v[k] = cmulf(b[k], w);
        w = cmulf(w, step);
    }
    // --- 32-point cross-lane DIF radix-2 (5 stages), output bit-reversed
#pragma unroll
    for (int h = 16; h > 0; h >>= 1) {
        float sh, ch;
        __sincosf(-PI_F * (float)(lane & (h - 1)) / (float)h, &sh, &ch);
        const float2 tw = make_float2(ch, sh);
        const bool hi = (lane & h) != 0;
#pragma unroll
        for (int k = 0; k < 7; k++) {
            float2 o;
            o.x = __shfl_xor_sync(0xffffffffu, v[k].x, h);
            o.y = __shfl_xor_sync(0xffffffffu, v[k].y, h);
            if (hi) {
                float2 d = make_float2(o.x - v[k].x, o.y - v[k].y);
                v[k] = cmulf(d, tw);
            } else {
                v[k].x += o.x;
                v[k].y += o.y;
            }
        }
    }
}

// ---------------- kernel 1: phase = (pred @ zernike) * mask ------------------
__global__ __launch_bounds__(256) void phase_kernel(
    const float* __restrict__ pred,
    const float* __restrict__ zern,
    const float* __restrict__ mask)
{
    __shared__ float sp[BATCH][36];   // padded rows
    const int tid = threadIdx.x;
    for (int i = tid; i < BATCH * NMODE; i += 256)
        sp[i / NMODE][i % NMODE] = pred[i];
    __syncthreads();

    const int p = blockIdx.x * 256 + tid;   // 196*256 == 50176 exactly
    float z[NMODE];
#pragma unroll
    for (int m = 0; m < NMODE; m++) z[m] = zern[(size_t)m * PP + p];
    const float mk = mask[p];

    for (int b = 0; b < BATCH; b++) {
        const float4* pb = reinterpret_cast<const float4*>(&sp[b][0]);
        float acc = 0.f;
#pragma unroll
        for (int q = 0; q < 8; q++) {
            float4 f = pb[q];
            acc += f.x * z[4*q+0] + f.y * z[4*q+1] + f.z * z[4*q+2] + f.w * z[4*q+3];
        }
        acc += sp[b][32] * z[32] + sp[b][33] * z[33] + sp[b][34] * z[34];
        g_phase[(size_t)b * PP + p] = acc * mk;
    }
}

// ---------------- kernel 2: per-row field + row FFT (both variants) ----------
__global__ __launch_bounds__(256) void row_kernel(const float* __restrict__ mask)
{
    const int gw   = blockIdx.x * 8 + (threadIdx.x >> 5);  // 0 .. 128*224-1
    const int lane = threadIdx.x & 31;
    const int b = gw / PDIM;
    const int h = gw % PDIM;

    const float* ph = g_phase + (size_t)b * PP + (size_t)h * PDIM;
    const float y  = (float)h * (2.0f / 223.0f) - 1.0f;
    const float y2 = y * y;

    float phi[7], mk[7], dfc[7];
#pragma unroll
    for (int j = 0; j < 7; j++) {
        const int w = 32 * j + lane;
        phi[j] = ph[w];
        mk[j]  = mask[h * PDIM + w];
        const float x = (float)w * (2.0f / 223.0f) - 1.0f;
        dfc[j] = 2.0f * (x * x + y2) - 1.0f;   // DEFOCUS_RAD = 1.0
    }
    const int rev = (int)(__brev((unsigned)lane) >> 27);

    // variant 0: in-focus
    {
        float2 v[7];
#pragma unroll
        for (int j = 0; j < 7; j++) {
            float s, c; __sincosf(phi[j], &s, &c);
            v[j] = make_float2(mk[j] * c, mk[j] * s);
        }
        fft224(v, lane);
        __half2* o = g_work + (size_t)(2 * b) * PP + (size_t)h * PDIM + 7 * rev;
#pragma unroll
        for (int k = 0; k < 7; k++) o[k] = __floats2half2_rn(v[k].x, v[k].y);
    }
    // variant 1: defocused
    {
        float2 v[7];
#pragma unroll
        for (int j = 0; j < 7; j++) {
            float s, c; __sincosf(phi[j] + dfc[j], &s, &c);
            v[j] = make_float2(mk[j] * c, mk[j] * s);
        }
        fft224(v, lane);
        __half2* o = g_work + (size_t)(2 * b + 1) * PP + (size_t)h * PDIM + 7 * rev;
#pragma unroll
        for (int k = 0; k < 7; k++) o[k] = __floats2half2_rn(v[k].x, v[k].y);
    }
}

// ---------------- kernel 3: column FFT + fused psf statistics ----------------
// For each (img, 16-column chunk): column FFTs, then accumulate
//   S = sum psf, A = sum psf^2, C = sum psf * t_shifted, T2 = sum t^2
// (fftshift folded into t index remap: shifted idx = (idx+112)%224)
__global__ __launch_bounds__(512) void col_kernel(const float* __restrict__ psfs)
{
    const int img   = blockIdx.x / CHUNKS;   // img = 2*b + var
    const int chunk = blockIdx.x % CHUNKS;
    const int v0    = chunk * CW;

    __shared__ __half2 tile [PDIM][CW + 1];  // 15232 B, 4B elems, stride 17 words
    __shared__ float   ttile[PDIM][CW + 1];  // 15232 B
    __shared__ float   red[16 * 4];

    const int tid = threadIdx.x;
    const __half2* src = g_work + (size_t)img * PP;
    const float*   t   = psfs   + (size_t)img * PP;
    const int tc0 = (v0 + 112) % 224;        // chunk-aligned, no wrap within chunk

    for (int i = tid; i < PDIM * CW; i += 512) {
        const int h = i / CW, c = i % CW;
        tile [h][c] = src[h * PDIM + v0 + c];
        ttile[h][c] = t  [h * PDIM + tc0 + c];
    }
    __syncthreads();

    const int warp = tid >> 5, lane = tid & 31;
    float2 v[7];
#pragma unroll
    for (int j = 0; j < 7; j++) {
        const float2 f = __half22float2(tile[32 * j + lane][warp]);
        v[j] = f;
    }
    fft224(v, lane);

    const int rev = (int)(__brev((unsigned)lane) >> 27);
    float S = 0.f, A = 0.f, C = 0.f, T2 = 0.f;
#pragma unroll
    for (int k = 0; k < 7; k++) {
        const int u  = 7 * rev + k;
        const int us = (u >= 112) ? (u - 112) : (u + 112);
        const float p  = v[k].x * v[k].x + v[k].y * v[k].y;
        const float tv = ttile[us][warp];
        S += p; A += p * p; C += p * tv; T2 += tv * tv;
    }
#pragma unroll
    for (int off = 16; off > 0; off >>= 1) {
        S  += __shfl_down_sync(0xffffffffu, S,  off);
        A  += __shfl_down_sync(0xffffffffu, A,  off);
        C  += __shfl_down_sync(0xffffffffu, C,  off);
        T2 += __shfl_down_sync(0xffffffffu, T2, off);
    }
    if (lane == 0) {
        red[warp * 4 + 0] = S;  red[warp * 4 + 1] = A;
        red[warp * 4 + 2] = C;  red[warp * 4 + 3] = T2;
    }
    __syncthreads();
    if (tid == 0) {
        float s = 0.f, a = 0.f, c = 0.f, t2 = 0.f;
#pragma unroll
        for (int w = 0; w < 16; w++) {
            s += red[w * 4 + 0]; a += red[w * 4 + 1];
            c += red[w * 4 + 2]; t2 += red[w * 4 + 3];
        }
        // transposed: [chunk][img] for coalesced float4 reads in final pass
        float* dst = g_part + (size_t)(chunk * NIMG + img) * 4;
        dst[0] = s; dst[1] = a; dst[2] = c; dst[3] = t2;
    }
}

// ---------------- kernel 4: z_loss + deterministic final combine -------------
__global__ __launch_bounds__(256) void final_kernel(
    const float* __restrict__ pred,
    const float* __restrict__ target,
    float* __restrict__ out)
{
    __shared__ float sh[256];
    const int tid = threadIdx.x;

    // sign-weighted MSE partial
    float zs = 0.f;
#pragma unroll
    for (int q = 0; q < BATCH * NMODE / 256 + 1; q++) {
        const int i = q * 256 + tid;
        if (i < BATCH * NMODE) {
            const float p = pred[i], t = target[i];
            const float d = p - t;
            const float w = (p * t < 0.f) ? 10.0f : 1.0f;
            zs += d * d * w;
        }
    }

    // per-image recon contribution: A/S'^2 - 2C/S' + T2 (coalesced float4)
    const float4* gp4 = reinterpret_cast<const float4*>(g_part);
    float s = 0.f, a = 0.f, c = 0.f, t2 = 0.f;
#pragma unroll
    for (int ch = 0; ch < CHUNKS; ch++) {
        const float4 q = gp4[ch * NIMG + tid];
        s += q.x; a += q.y; c += q.z; t2 += q.w;
    }
    const float sp = s + 1e-8f;
    float rc = a / (sp * sp) - 2.0f * c / sp + t2;

    sh[tid] = zs; __syncthreads();
    for (int off = 128; off > 0; off >>= 1) {
        if (tid < off) sh[tid] += sh[tid + off];
        __syncthreads();
    }
    const float zloss = sh[0] / (float)(BATCH * NMODE);
    __syncthreads();

    sh[tid] = rc; __syncthreads();
    for (int off = 128; off > 0; off >>= 1) {
        if (tid < off) sh[tid] += sh[tid + off];
        __syncthreads();
    }
    if (tid == 0) {
        const float recon = sh[0] / ((float)BATCH * (float)PP);
        out[0] = zloss + 0.4f * recon;
    }
}

// ---------------- launch ------------------------------------------------------
extern "C" void kernel_launch(void* const* d_in, const int* in_sizes, int n_in,
                              void* d_out, int out_size)
{
    const float* pred   = (const float*)d_in[0];
    const float* target = (const float*)d_in[1];
    const float* psfs   = (const float*)d_in[2];
    const float* zern   = (const float*)d_in[3];
    const float* mask   = (const float*)d_in[4];
    float* out = (float*)d_out;

    phase_kernel<<<196, 256>>>(pred, zern, mask);
    row_kernel  <<<BATCH * PDIM / 8, 256>>>(mask);
    col_kernel  <<<NIMG * CHUNKS, 512>>>(psfs);
    final_kernel<<<1, 256>>>(pred, target, out);
}

// round 3
// speedup vs baseline: 1.7189x; 1.2705x over previous
#include <cuda_runtime.h>
#include <cuda_fp16.h>
#include <math.h>
#include <stdint.h>

#define PDIM 224
#define PP   (PDIM*PDIM)
#define BATCH 128
#define NMODE 35
#define NIMG  256          // 128 batch * 2 variants, img = 2*b + var
#define PI_F 3.14159265358979323846f
#define TILE_PITCH 225     // half2 units; 225 mod 32 == 1 -> conflict-free cols
#define SMEM_BYTES (PDIM * TILE_PITCH * 4)

// ---------------- scratch (static device globals; no runtime alloc) ----------
__device__ __half g_phase[BATCH * PP];   // 12.8 MB
__device__ float  g_rc[NIMG];            // per-image recon contribution

__device__ __forceinline__ float2 cmulf(float2 a, float2 b) {
    return make_float2(a.x*b.x - a.y*b.y, a.x*b.y + a.y*b.x);
}

// 224-point forward FFT (e^{-i}) held by one warp.
// Input:  v[j] = x[32*j + lane], j=0..6
// Output: v[k1] = X[7*bitrev5(lane) + k1]
__device__ __forceinline__ void fft224(float2 v[7], int lane) {
    // --- symmetric radix-7 DFT within thread ---
    const float C1 =  0.62348980185873359f, C2 = -0.22252093395631440f, C3 = -0.90096886790241915f;
    const float S1 =  0.78183148246802981f, S2 =  0.97492791218182362f, S3 =  0.43388373911755812f;
    const float2 v0 = v[0];
    float2 s1, s2, s3, d1, d2, d3;
    s1.x = v[1].x + v[6].x; s1.y = v[1].y + v[6].y;
    d1.x = v[1].x - v[6].x; d1.y = v[1].y - v[6].y;
    s2.x = v[2].x + v[5].x; s2.y = v[2].y + v[5].y;
    d2.x = v[2].x - v[5].x; d2.y = v[2].y - v[5].y;
    s3.x = v[3].x + v[4].x; s3.y = v[3].y + v[4].y;
    d3.x = v[3].x - v[4].x; d3.y = v[3].y - v[4].y;

    float2 A1, A2, A3, B1, B2, B3;
    A1.x = v0.x + C1*s1.x + C2*s2.x + C3*s3.x;  A1.y = v0.y + C1*s1.y + C2*s2.y + C3*s3.y;
    A2.x = v0.x + C2*s1.x + C3*s2.x + C1*s3.x;  A2.y = v0.y + C2*s1.y + C3*s2.y + C1*s3.y;
    A3.x = v0.x + C3*s1.x + C1*s2.x + C2*s3.x;  A3.y = v0.y + C3*s1.y + C1*s2.y + C2*s3.y;
    B1.x = S1*d1.x + S2*d2.x + S3*d3.x;         B1.y = S1*d1.y + S2*d2.y + S3*d3.y;
    B2.x = S2*d1.x - S3*d2.x - S1*d3.x;         B2.y = S2*d1.y - S3*d2.y - S1*d3.y;
    B3.x = S3*d1.x - S1*d2.x + S2*d3.x;         B3.y = S3*d1.y - S1*d2.y + S2*d3.y;

    v[0].x = v0.x + s1.x + s2.x + s3.x;  v[0].y = v0.y + s1.y + s2.y + s3.y;
    // X[k] = A - iB ; X[7-k] = A + iB
    v[1] = make_float2(A1.x + B1.y, A1.y - B1.x);
    v[6] = make_float2(A1.x - B1.y, A1.y + B1.x);
    v[2] = make_float2(A2.x + B2.y, A2.y - B2.x);
    v[5] = make_float2(A2.x - B2.y, A2.y + B2.x);
    v[3] = make_float2(A3.x + B3.y, A3.y - B3.x);
    v[4] = make_float2(A3.x - B3.y, A3.y + B3.x);

    // --- twiddle W224^{lane*k1}, built incrementally ---
    float sa, ca;
    __sincosf(-2.0f * PI_F * (float)lane / 224.0f, &sa, &ca);
    const float2 step = make_float2(ca, sa);
    float2 w = make_float2(1.f, 0.f);
#pragma unroll
    for (int k = 0; k < 7; k++) {
        v[k] = cmulf(v[k], w);
        w = cmulf(w, step);
    }
    // --- 32-point cross-lane DIF radix-2 (5 stages), output bit-reversed ---
#pragma unroll
    for (int h = 16; h > 0; h >>= 1) {
        float sh, ch;
        __sincosf(-PI_F * (float)(lane & (h - 1)) / (float)h, &sh, &ch);
        const float2 tw = make_float2(ch, sh);
        const bool hi = (lane & h) != 0;
#pragma unroll
        for (int k = 0; k < 7; k++) {
            float2 o;
            o.x = __shfl_xor_sync(0xffffffffu, v[k].x, h);
            o.y = __shfl_xor_sync(0xffffffffu, v[k].y, h);
            if (hi) {
                float2 d = make_float2(o.x - v[k].x, o.y - v[k].y);
                v[k] = cmulf(d, tw);
            } else {
                v[k].x += o.x;
                v[k].y += o.y;
            }
        }
    }
}

// ---------------- kernel 1: phase = (pred @ zernike) * mask (half out) -------
__global__ __launch_bounds__(256) void phase_kernel(
    const float* __restrict__ pred,
    const float* __restrict__ zern,
    const float* __restrict__ mask)
{
    __shared__ float sp[BATCH][36];
    const int tid = threadIdx.x;
    for (int i = tid; i < BATCH * NMODE; i += 256)
        sp[i / NMODE][i % NMODE] = pred[i];
    __syncthreads();

    const int p = blockIdx.x * 256 + tid;   // 196*256 == 50176 exactly
    float z[NMODE];
#pragma unroll
    for (int m = 0; m < NMODE; m++) z[m] = zern[(size_t)m * PP + p];
    const float mk = mask[p];

    for (int b = 0; b < BATCH; b++) {
        const float4* pb = reinterpret_cast<const float4*>(&sp[b][0]);
        float acc = 0.f;
#pragma unroll
        for (int q = 0; q < 8; q++) {
            float4 f = pb[q];
            acc += f.x * z[4*q+0] + f.y * z[4*q+1] + f.z * z[4*q+2] + f.w * z[4*q+3];
        }
        acc += sp[b][32] * z[32] + sp[b][33] * z[33] + sp[b][34] * z[34];
        g_phase[(size_t)b * PP + p] = __float2half(acc * mk);
    }
}

// ---------------- kernel 2: fused per-image 2D FFT + psf statistics ----------
// One block per image (img = 2*b + var). Row FFTs -> smem tile (half2) ->
// column FFTs -> |.|^2 written back into tile as fp32 -> coalesced fused
// statistics (S, A=sum psf^2, C=sum psf*t_shift, T2=sum t^2) -> rc per image.
extern __shared__ __align__(16) unsigned char smem_raw[];

__global__ __launch_bounds__(512, 1) void psf_kernel(
    const float* __restrict__ psfs,
    const float* __restrict__ mask)
{
    __half2* tile = reinterpret_cast<__half2*>(smem_raw);
    float*   pf   = reinterpret_cast<float*>(smem_raw);
    __shared__ float red[16 * 4];

    const int img  = blockIdx.x;
    const int b    = img >> 1;
    const int var  = img & 1;
    const int warp = threadIdx.x >> 5, lane = threadIdx.x & 31;
    const int rev  = (int)(__brev((unsigned)lane) >> 27);

    const __half* ph = g_phase + (size_t)b * PP;

    // --- row stage: 14 rows per warp ---
#pragma unroll 1
    for (int r = 0; r < 14; r++) {
        const int h = warp * 14 + r;
        const float y  = (float)h * (2.0f / 223.0f) - 1.0f;
        const float y2 = y * y;
        float2 v[7];
#pragma unroll
        for (int j = 0; j < 7; j++) {
            const int w = 32 * j + lane;
            float phi = __half2float(ph[h * PDIM + w]);
            const float m = mask[h * PDIM + w];
            if (var) {
                const float x = (float)w * (2.0f / 223.0f) - 1.0f;
                phi += 2.0f * (x * x + y2) - 1.0f;   // DEFOCUS_RAD = 1.0
            }
            float s, c; __sincosf(phi, &s, &c);
            v[j] = make_float2(m * c, m * s);
        }
        fft224(v, lane);
        __half2* o = tile + h * TILE_PITCH + 7 * rev;
#pragma unroll
        for (int k = 0; k < 7; k++) o[k] = __floats2half2_rn(v[k].x, v[k].y);
    }
    __syncthreads();

    // --- column stage: 14 columns per warp; write |field|^2 back as fp32 ---
#pragma unroll 1
    for (int r = 0; r < 14; r++) {
        const int c = warp * 14 + r;
        float2 v[7];
#pragma unroll
        for (int j = 0; j < 7; j++)
            v[j] = __half22float2(tile[(32 * j + lane) * TILE_PITCH + c]);
        fft224(v, lane);
#pragma unroll
        for (int k = 0; k < 7; k++) {
            const int u = 7 * rev + k;
            pf[u * TILE_PITCH + c] = v[k].x * v[k].x + v[k].y * v[k].y;
        }
    }
    __syncthreads();

    // --- fused statistics, coalesced ---
    const float* t = psfs + (size_t)img * PP;
    float S = 0.f, A = 0.f, C = 0.f, T2 = 0.f;
    for (int i = threadIdx.x; i < PP; i += 512) {
        const int r = i / PDIM;
        const int c = i - r * PDIM;
        const float p = pf[r * TILE_PITCH + c];
        int us = r + 112; if (us >= PDIM) us -= PDIM;
        int cs = c + 112; if (cs >= PDIM) cs -= PDIM;
        const float tv = t[us * PDIM + cs];
        S += p; A += p * p; C += p * tv; T2 += tv * tv;
    }
#pragma unroll
    for (int off = 16; off > 0; off >>= 1) {
        S  += __shfl_down_sync(0xffffffffu, S,  off);
        A  += __shfl_down_sync(0xffffffffu, A,  off);
        C  += __shfl_down_sync(0xffffffffu, C,  off);
        T2 += __shfl_down_sync(0xffffffffu, T2, off);
    }
    if (lane == 0) {
        red[warp * 4 + 0] = S;  red[warp * 4 + 1] = A;
        red[warp * 4 + 2] = C;  red[warp * 4 + 3] = T2;
    }
    __syncthreads();
    if (threadIdx.x == 0) {
        float s = 0.f, a = 0.f, c = 0.f, t2 = 0.f;
#pragma unroll
        for (int w = 0; w < 16; w++) {
            s += red[w * 4 + 0]; a += red[w * 4 + 1];
            c += red[w * 4 + 2]; t2 += red[w * 4 + 3];
        }
        const float sp = s + 1e-8f;
        g_rc[img] = a / (sp * sp) - 2.0f * c / sp + t2;
    }
}

// ---------------- kernel 3: z_loss + final combine ---------------------------
__global__ __launch_bounds__(256) void final_kernel(
    const float* __restrict__ pred,
    const float* __restrict__ target,
    float* __restrict__ out)
{
    __shared__ float sh[256];
    const int tid = threadIdx.x;

    float zs = 0.f;
#pragma unroll
    for (int q = 0; q < (BATCH * NMODE + 255) / 256; q++) {
        const int i = q * 256 + tid;
        if (i < BATCH * NMODE) {
            const float p = pred[i], t = target[i];
            const float d = p - t;
            const float w = (p * t < 0.f) ? 10.0f : 1.0f;
            zs += d * d * w;
        }
    }
    const float rc = g_rc[tid];   // 256 threads == NIMG

    sh[tid] = zs; __syncthreads();
    for (int off = 128; off > 0; off >>= 1) {
        if (tid < off) sh[tid] += sh[tid + off];
        __syncthreads();
    }
    const float zloss = sh[0] / (float)(BATCH * NMODE);
    __syncthreads();

    sh[tid] = rc; __syncthreads();
    for (int off = 128; off > 0; off >>= 1) {
        if (tid < off) sh[tid] += sh[tid + off];
        __syncthreads();
    }
    if (tid == 0) {
        const float recon = sh[0] / ((float)BATCH * (float)PP);
        out[0] = zloss + 0.4f * recon;
    }
}

// ---------------- launch ------------------------------------------------------
extern "C" void kernel_launch(void* const* d_in, const int* in_sizes, int n_in,
                              void* d_out, int out_size)
{
    const float* pred   = (const float*)d_in[0];
    const float* target = (const float*)d_in[1];
    const float* psfs   = (const float*)d_in[2];
    const float* zern   = (const float*)d_in[3];
    const float* mask   = (const float*)d_in[4];
    float* out = (float*)d_out;

    cudaFuncSetAttribute(psf_kernel,
                         cudaFuncAttributeMaxDynamicSharedMemorySize, SMEM_BYTES);

    phase_kernel<<<196, 256>>>(pred, zern, mask);
    psf_kernel  <<<NIMG, 512, SMEM_BYTES>>>(psfs, mask);
    final_kernel<<<1, 256>>>(pred, target, out);
}